// round 4
// baseline (speedup 1.0000x reference)
#include <cuda_runtime.h>

#define NB 8
#define NC 16
#define NH 512
#define NW 512
#define NHW (NH * NW)
#define KCAP 16
#define MAXOVF (1 << 20)

#define TX 64
#define TY 16
#define RX (TX + 6)            // 70  : src x range [X-3, X+66]
#define RY (TY + 6)            // 22  : src y range [Y-3, Y+18]
#define PLANE (RX * RY)        // 1540
#define PSTRIDE (PLANE + 1)    // 1541 (pad to break bank periodicity)
#define SMEM_BYTES (NC * PSTRIDE * 4)   // 98,624 B

// Per-destination-cell bins (static device scratch — allowed).
__device__ int    g_cnt[NB * NHW];
__device__ float4 g_rec[(size_t)NB * NHW * KCAP];
__device__ int    g_ovf_cnt;
__device__ float4 g_ovf[MAXOVF];

// ---------------------------------------------------------------------------
// Kernel 1: zero counters
// ---------------------------------------------------------------------------
__global__ void k_zero_cnt() {
    int i = blockIdx.x * blockDim.x + threadIdx.x;
    ((int4*)g_cnt)[i] = make_int4(0, 0, 0, 0);
    if (i == 0) g_ovf_cnt = 0;
}

// ---------------------------------------------------------------------------
// Kernel 2: bin sources by destination cell. Small-flow records go to bins;
// large-flow (>|3|) or bin-overflow sources go to the rare global list.
// ---------------------------------------------------------------------------
__global__ void k_bin(const float* __restrict__ flow) {
    int x = blockIdx.x * blockDim.x + threadIdx.x;
    int y = blockIdx.y;
    int b = blockIdx.z;

    int pix = (b * NH + y) * NW + x;
    float2 f = __ldg((const float2*)flow + pix);

    float xd = (float)x + f.x;
    float yd = (float)y + f.y;
    float x0f = floorf(xd), y0f = floorf(yd);
    int x0 = (int)x0f, y0 = (int)y0f;

    // Reference semantics: scatter only if ALL four corners in-bounds
    if (x0 < 0 || x0 > NW - 2 || y0 < 0 || y0 > NH - 2) return;

    float fx = xd - x0f, fy = yd - y0f;
    int cell = (b * NH + y0) * NW + x0;
    unsigned src_xy = (unsigned)(y * NW + x);

    bool small = (fabsf(f.x) < 3.0f) && (fabsf(f.y) < 3.0f);
    int slot = KCAP;
    if (small) slot = atomicAdd(&g_cnt[cell], 1);

    if (small && slot < KCAP) {
        g_rec[(size_t)cell * KCAP + slot] =
            make_float4(__uint_as_float(src_xy), fx, fy, 0.f);
    } else {
        int o = atomicAdd(&g_ovf_cnt, 1);
        if (o < MAXOVF) {
            unsigned packed = ((unsigned)b << 18) | (unsigned)(y0 * NW + x0);
            g_ovf[o] = make_float4(__uint_as_float(src_xy), fx, fy,
                                   __uint_as_float(packed));
        }
    }
}

// ---------------------------------------------------------------------------
// Kernel 3: tiled gather. CTA = 64x16 dest tile. Stage im0 region
// (70x22 x 16ch) into smem in channel-plane layout (coalesced STS,
// near-conflict-free random LDS). Then each thread accumulates its dest
// pixel from the 4 neighbor cells' records, reading channels from smem,
// and writes BCHW output (+ im1) coalesced. No atomics.
// ---------------------------------------------------------------------------
__global__ __launch_bounds__(1024) void k_gather(const float* __restrict__ im0,
                                                 const float* __restrict__ im1,
                                                 float* __restrict__ out) {
    extern __shared__ float s[];   // [NC][PSTRIDE]

    int X = blockIdx.x * TX;
    int Y = blockIdx.y * TY;
    int b = blockIdx.z;

    int tid = threadIdx.y * TX + threadIdx.x;
    const float* im0b = im0 + (size_t)b * NC * NHW;

    // ---- stage im0 region: NC*PLANE = 24640 elements, 1024 threads ----
    for (int e = tid; e < NC * PLANE; e += TX * TY) {
        int c   = e / PLANE;
        int rem = e - c * PLANE;
        int py  = rem / RX;
        int px  = rem - py * RX;
        int gx = X - 3 + px;
        int gy = Y - 3 + py;
        float v = 0.f;
        if (gx >= 0 && gx < NW && gy >= 0 && gy < NH)
            v = __ldg(im0b + (size_t)c * NHW + gy * NW + gx);
        s[c * PSTRIDE + rem] = v;
    }
    __syncthreads();

    int x = X + threadIdx.x;
    int y = Y + threadIdx.y;

    float acc[NC];
#pragma unroll
    for (int c = 0; c < NC; ++c) acc[c] = 0.f;

#pragma unroll
    for (int dy = 0; dy < 2; ++dy) {
        int cy = y - dy;
        if (cy < 0) continue;
#pragma unroll
        for (int dx = 0; dx < 2; ++dx) {
            int cx = x - dx;
            if (cx < 0) continue;
            int cell = (b * NH + cy) * NW + cx;
            int n = min(g_cnt[cell], KCAP);
            const float4* rp = g_rec + (size_t)cell * KCAP;
            for (int i = 0; i < n; ++i) {
                float4 r = rp[i];
                unsigned src_xy = __float_as_uint(r.x);
                int sy = src_xy >> 9;          // NW = 512
                int sx = src_xy & 511;
                float wx = dx ? r.y : 1.f - r.y;
                float wy = dy ? r.z : 1.f - r.z;
                float w = wx * wy;
                int off = (sy - (Y - 3)) * RX + (sx - (X - 3));
#pragma unroll
                for (int c = 0; c < NC; ++c)
                    acc[c] += w * s[c * PSTRIDE + off];
            }
        }
    }

    size_t o = (size_t)b * NC * NHW + (size_t)y * NW + x;
#pragma unroll
    for (int c = 0; c < NC; ++c)
        out[o + (size_t)c * NHW] = acc[c] + __ldg(im1 + o + (size_t)c * NHW);
}

// ---------------------------------------------------------------------------
// Kernel 4: rare fallback sources (large flow / bin overflow) -> global
// atomics on the final BCHW output. Runs after k_gather.
// ---------------------------------------------------------------------------
__global__ void k_ovf(const float* __restrict__ im0, float* __restrict__ out) {
    int total = min(g_ovf_cnt, MAXOVF);
    for (int i = blockIdx.x * blockDim.x + threadIdx.x; i < total;
         i += gridDim.x * blockDim.x) {
        float4 r = g_ovf[i];
        unsigned src_xy = __float_as_uint(r.x);
        unsigned packed = __float_as_uint(r.w);
        int b = packed >> 18;
        int cell = packed & 0x3FFFF;
        int y0 = cell >> 9, x0 = cell & 511;
        float fx = r.y, fy = r.z;
        const float* sp = im0 + (size_t)b * NC * NHW + src_xy;
        float* ob = out + (size_t)b * NC * NHW;
#pragma unroll
        for (int dy = 0; dy < 2; ++dy) {
#pragma unroll
            for (int dx = 0; dx < 2; ++dx) {
                float w = (dx ? fx : 1.f - fx) * (dy ? fy : 1.f - fy);
                float* op = ob + (size_t)(y0 + dy) * NW + (x0 + dx);
                for (int c = 0; c < NC; ++c)
                    atomicAdd(op + (size_t)c * NHW, w * __ldg(sp + (size_t)c * NHW));
            }
        }
    }
}

// ---------------------------------------------------------------------------
extern "C" void kernel_launch(void* const* d_in, const int* in_sizes, int n_in,
                              void* d_out, int out_size) {
    const float* im0  = (const float*)d_in[0];
    const float* flow = (const float*)d_in[1];
    const float* im1  = (const float*)d_in[2];
    float* out = (float*)d_out;

    cudaFuncSetAttribute(k_gather, cudaFuncAttributeMaxDynamicSharedMemorySize,
                         SMEM_BYTES);

    k_zero_cnt<<<2048, 256>>>();
    k_bin<<<dim3(NW / 256, NH, NB), 256>>>(flow);
    k_gather<<<dim3(NW / TX, NH / TY, NB), dim3(TX, TY), SMEM_BYTES>>>(im0, im1, out);
    k_ovf<<<64, 256>>>(im0, out);
}

// round 5
// speedup vs baseline: 1.1582x; 1.1582x over previous
#include <cuda_runtime.h>

#define NB 8
#define NC 16
#define NH 512
#define NW 512
#define NHW (NH * NW)
#define KCAP 16
#define MAXOVF (1 << 20)

#define TX 32
#define TY 8
#define RX (TX + 6)            // 38 : src x range [X-3, X+34]
#define RY (TY + 6)            // 14 : src y range [Y-3, Y+10]
#define PLANE (RX * RY)        // 532
#define PSTRIDE 533            // odd stride -> conflict-free near-consecutive LDS
#define SMEM_FLOATS (NC * PSTRIDE)   // 8528 floats = 34.1 KB

// Per-destination-cell bins (static device scratch — allowed).
__device__ int    g_cnt[NB * NHW];
__device__ float4 g_rec[(size_t)NB * NHW * KCAP];
__device__ int    g_ovf_cnt;
__device__ float4 g_ovf[MAXOVF];

// ---------------------------------------------------------------------------
// Kernel 1: zero counters
// ---------------------------------------------------------------------------
__global__ void k_zero_cnt() {
    int i = blockIdx.x * blockDim.x + threadIdx.x;
    ((int4*)g_cnt)[i] = make_int4(0, 0, 0, 0);
    if (i == 0) g_ovf_cnt = 0;
}

// ---------------------------------------------------------------------------
// Kernel 2: bin sources by destination cell. Small-flow records go to bins;
// large-flow (>=|3|) or bin-overflow sources go to the rare global list.
// ---------------------------------------------------------------------------
__global__ void k_bin(const float* __restrict__ flow) {
    int x = blockIdx.x * blockDim.x + threadIdx.x;
    int y = blockIdx.y;
    int b = blockIdx.z;

    int pix = (b * NH + y) * NW + x;
    float2 f = __ldg((const float2*)flow + pix);

    float xd = (float)x + f.x;
    float yd = (float)y + f.y;
    float x0f = floorf(xd), y0f = floorf(yd);
    int x0 = (int)x0f, y0 = (int)y0f;

    // Reference semantics: scatter only if ALL four corners in-bounds
    if (x0 < 0 || x0 > NW - 2 || y0 < 0 || y0 > NH - 2) return;

    float fx = xd - x0f, fy = yd - y0f;
    int cell = (b * NH + y0) * NW + x0;
    unsigned src_xy = (unsigned)(y * NW + x);

    bool small = (fabsf(f.x) < 3.0f) && (fabsf(f.y) < 3.0f);
    int slot = KCAP;
    if (small) slot = atomicAdd(&g_cnt[cell], 1);

    if (small && slot < KCAP) {
        g_rec[(size_t)cell * KCAP + slot] =
            make_float4(__uint_as_float(src_xy), fx, fy, 0.f);
    } else {
        int o = atomicAdd(&g_ovf_cnt, 1);
        if (o < MAXOVF) {
            unsigned packed = ((unsigned)b << 18) | (unsigned)(y0 * NW + x0);
            g_ovf[o] = make_float4(__uint_as_float(src_xy), fx, fy,
                                   __uint_as_float(packed));
        }
    }
}

// ---------------------------------------------------------------------------
// Kernel 3: tiled gather. CTA = 32x8 dest tile, 256 threads, one dest pixel
// per thread (acc[16] stays in registers — no launch_bounds reg cap).
// Stage im0 region (38x14 x 16ch = 34KB) into smem channel-plane layout,
// then accumulate from the 4 neighbor cells' records via LDS, write BCHW
// output (+ im1) coalesced. No atomics.
// ---------------------------------------------------------------------------
__global__ __launch_bounds__(256) void k_gather(const float* __restrict__ im0,
                                                const float* __restrict__ im1,
                                                float* __restrict__ out) {
    __shared__ float s[SMEM_FLOATS];

    int X = blockIdx.x * TX;
    int Y = blockIdx.y * TY;
    int b = blockIdx.z;

    int tid = threadIdx.y * TX + threadIdx.x;
    const float* im0b = im0 + (size_t)b * NC * NHW;

    // ---- stage im0 region: NC*PLANE = 8512 elements, 256 threads ----
    for (int e = tid; e < NC * PLANE; e += TX * TY) {
        int c   = e / PLANE;
        int rem = e - c * PLANE;
        int py  = rem / RX;
        int px  = rem - py * RX;
        int gx = X - 3 + px;
        int gy = Y - 3 + py;
        float v = 0.f;
        if (gx >= 0 && gx < NW && gy >= 0 && gy < NH)
            v = __ldg(im0b + (size_t)c * NHW + gy * NW + gx);
        s[c * PSTRIDE + py * RX + px] = v;
    }
    __syncthreads();

    int x = X + threadIdx.x;
    int y = Y + threadIdx.y;

    float acc[NC];
#pragma unroll
    for (int c = 0; c < NC; ++c) acc[c] = 0.f;

#pragma unroll
    for (int dy = 0; dy < 2; ++dy) {
        int cy = y - dy;
        if (cy < 0) continue;
#pragma unroll
        for (int dx = 0; dx < 2; ++dx) {
            int cx = x - dx;
            if (cx < 0) continue;
            int cell = (b * NH + cy) * NW + cx;
            int n = min(__ldg(&g_cnt[cell]), KCAP);
            const float4* rp = g_rec + (size_t)cell * KCAP;
            for (int i = 0; i < n; ++i) {
                float4 r = __ldg(rp + i);
                unsigned src_xy = __float_as_uint(r.x);
                int sy = src_xy >> 9;          // NW = 512
                int sx = src_xy & 511;
                float wx = dx ? r.y : 1.f - r.y;
                float wy = dy ? r.z : 1.f - r.z;
                float w = wx * wy;
                int off = (sy - (Y - 3)) * RX + (sx - (X - 3));
#pragma unroll
                for (int c = 0; c < NC; ++c)
                    acc[c] += w * s[c * PSTRIDE + off];
            }
        }
    }

    size_t o = (size_t)b * NC * NHW + (size_t)y * NW + x;
#pragma unroll
    for (int c = 0; c < NC; ++c)
        out[o + (size_t)c * NHW] = acc[c] + __ldg(im1 + o + (size_t)c * NHW);
}

// ---------------------------------------------------------------------------
// Kernel 4: rare fallback sources (large flow / bin overflow) -> global
// atomic adds on the final BCHW output. Runs after k_gather.
// ---------------------------------------------------------------------------
__global__ void k_ovf(const float* __restrict__ im0, float* __restrict__ out) {
    int total = min(g_ovf_cnt, MAXOVF);
    for (int i = blockIdx.x * blockDim.x + threadIdx.x; i < total;
         i += gridDim.x * blockDim.x) {
        float4 r = g_ovf[i];
        unsigned src_xy = __float_as_uint(r.x);
        unsigned packed = __float_as_uint(r.w);
        int b = packed >> 18;
        int cell = packed & 0x3FFFF;
        int y0 = cell >> 9, x0 = cell & 511;
        float fx = r.y, fy = r.z;
        const float* sp = im0 + (size_t)b * NC * NHW + src_xy;
        float* ob = out + (size_t)b * NC * NHW;
#pragma unroll
        for (int dy = 0; dy < 2; ++dy) {
#pragma unroll
            for (int dx = 0; dx < 2; ++dx) {
                float w = (dx ? fx : 1.f - fx) * (dy ? fy : 1.f - fy);
                float* op = ob + (size_t)(y0 + dy) * NW + (x0 + dx);
#pragma unroll
                for (int c = 0; c < NC; ++c)
                    atomicAdd(op + (size_t)c * NHW, w * __ldg(sp + (size_t)c * NHW));
            }
        }
    }
}

// ---------------------------------------------------------------------------
extern "C" void kernel_launch(void* const* d_in, const int* in_sizes, int n_in,
                              void* d_out, int out_size) {
    const float* im0  = (const float*)d_in[0];
    const float* flow = (const float*)d_in[1];
    const float* im1  = (const float*)d_in[2];
    float* out = (float*)d_out;

    k_zero_cnt<<<2048, 256>>>();
    k_bin<<<dim3(NW / 256, NH, NB), 256>>>(flow);
    k_gather<<<dim3(NW / TX, NH / TY, NB), dim3(TX, TY)>>>(im0, im1, out);
    k_ovf<<<256, 256>>>(im0, out);
}